// round 15
// baseline (speedup 1.0000x reference)
#include <cuda_runtime.h>

#define MAXN 50000
#define MAXE 800000
#define HD 64
#define NG 64
#define NO 32

// ---- scratch (static device memory; no allocation APIs) ----
__device__ __align__(16) float g_hw[MAXN * HD];   // GEMM output per layer
__device__ __align__(16) float g_h [MAXN * HD];   // aggregated features per layer
__device__ float g_dis[MAXN];                     // rsqrt(deg)
__device__ int   g_deg[MAXN];
__device__ int   g_rowptr[MAXN + 1];
__device__ int   g_cursor[MAXN];
__device__ int2  g_edge[MAXE];                    // (src, bitcast(norm)) bucketed by dst
__device__ float g_pooled[NG * HD];
__device__ float g_gcnt[NG];

// ---- init: zero counters/accumulators ----
__global__ void k_init(int n) {
    int i = blockIdx.x * blockDim.x + threadIdx.x;
    if (i < n)       g_deg[i]    = 0;
    if (i < NG * HD) g_pooled[i] = 0.f;
    if (i < NG)      g_gcnt[i]   = 0.f;
}

// ---- in-degree count (dst row of edge_index) ----
__global__ void k_count(const int* __restrict__ ei, int e) {
    int i = blockIdx.x * blockDim.x + threadIdx.x;
    if (i < e) atomicAdd(&g_deg[ei[e + i]], 1);
}

// ---- dis = rsqrt(deg + 1)  (self-loop) ----
__global__ void k_dis(int n) {
    int i = blockIdx.x * blockDim.x + threadIdx.x;
    if (i < n) g_dis[i] = rsqrtf((float)g_deg[i] + 1.0f);
}

// ---- exclusive scan of degrees -> rowptr, cursor (single block) ----
__global__ __launch_bounds__(1024) void k_scan(int n) {
    __shared__ int part[1024];
    int t = threadIdx.x;
    int ch = (n + 1023) >> 10;
    int base = t * ch;
    int s = 0;
    for (int j = 0; j < ch; j++) {
        int idx = base + j;
        if (idx < n) s += g_deg[idx];
    }
    part[t] = s;
    __syncthreads();
    for (int off = 1; off < 1024; off <<= 1) {
        int v = (t >= off) ? part[t - off] : 0;
        __syncthreads();
        part[t] += v;
        __syncthreads();
    }
    int run = (t == 0) ? 0 : part[t - 1];
    for (int j = 0; j < ch; j++) {
        int idx = base + j;
        if (idx < n) {
            g_rowptr[idx] = run;
            g_cursor[idx] = run;
            run += g_deg[idx];
        }
    }
    if (t == 0) g_rowptr[n] = part[1023];
}

// ---- bucket edges by dst; precompute norm = dis[src]*dis[dst] ----
__global__ void k_build(const int* __restrict__ ei, int e) {
    int i = blockIdx.x * blockDim.x + threadIdx.x;
    if (i >= e) return;
    int s = ei[i];
    int d = ei[e + i];
    int pos = atomicAdd(&g_cursor[d], 1);
    float w = g_dis[s] * g_dis[d];
    g_edge[pos] = make_int2(s, __float_as_int(w));
}

// ---- GEMM: g_hw = in(N,64) @ W(64,64); in = x or g_h ----
__device__ __forceinline__ float4 fma4(float a, float4 w, float4 acc) {
    acc.x = fmaf(a, w.x, acc.x);
    acc.y = fmaf(a, w.y, acc.y);
    acc.z = fmaf(a, w.z, acc.z);
    acc.w = fmaf(a, w.w, acc.w);
    return acc;
}

__global__ __launch_bounds__(256) void k_gemm64(const float* __restrict__ xin,
                                                const float* __restrict__ W,
                                                int n, int use_x) {
    __shared__ float4 Ws[1024];   // W[k][c4] as float4: Ws[k*16 + cg]
    int t = threadIdx.x;
    const float4* W4 = (const float4*)W;
#pragma unroll
    for (int i = 0; i < 4; i++) Ws[t + 256 * i] = W4[t + 256 * i];
    __syncthreads();

    const float4* in4 = (const float4*)(use_x ? xin : (const float*)g_h);
    int cg = t & 15;             // column group: cols 4*cg..4*cg+3
    int rq = t >> 4;             // 0..15
    int r0 = blockIdx.x * 64 + rq;  // rows r0, r0+16, r0+32, r0+48

    float4 z = make_float4(0.f, 0.f, 0.f, 0.f);
    float4 a0 = z, a1 = z, a2 = z, a3 = z;

#pragma unroll 4
    for (int kk = 0; kk < 16; kk++) {
        float4 x0 = (r0      < n) ? __ldg(&in4[(r0     ) * 16 + kk]) : z;
        float4 x1 = (r0 + 16 < n) ? __ldg(&in4[(r0 + 16) * 16 + kk]) : z;
        float4 x2 = (r0 + 32 < n) ? __ldg(&in4[(r0 + 32) * 16 + kk]) : z;
        float4 x3 = (r0 + 48 < n) ? __ldg(&in4[(r0 + 48) * 16 + kk]) : z;
        float4 w0 = Ws[(kk * 4 + 0) * 16 + cg];
        float4 w1 = Ws[(kk * 4 + 1) * 16 + cg];
        float4 w2 = Ws[(kk * 4 + 2) * 16 + cg];
        float4 w3 = Ws[(kk * 4 + 3) * 16 + cg];
        a0 = fma4(x0.x, w0, a0); a0 = fma4(x0.y, w1, a0); a0 = fma4(x0.z, w2, a0); a0 = fma4(x0.w, w3, a0);
        a1 = fma4(x1.x, w0, a1); a1 = fma4(x1.y, w1, a1); a1 = fma4(x1.z, w2, a1); a1 = fma4(x1.w, w3, a1);
        a2 = fma4(x2.x, w0, a2); a2 = fma4(x2.y, w1, a2); a2 = fma4(x2.z, w2, a2); a2 = fma4(x2.w, w3, a2);
        a3 = fma4(x3.x, w0, a3); a3 = fma4(x3.y, w1, a3); a3 = fma4(x3.z, w2, a3); a3 = fma4(x3.w, w3, a3);
    }

    float4* out4 = (float4*)g_hw;
    if (r0      < n) out4[(r0     ) * 16 + cg] = a0;
    if (r0 + 16 < n) out4[(r0 + 16) * 16 + cg] = a1;
    if (r0 + 32 < n) out4[(r0 + 32) * 16 + cg] = a2;
    if (r0 + 48 < n) out4[(r0 + 48) * 16 + cg] = a3;
}

// ---- aggregation (gather over CSR) + bias (+relu): g_h = agg(g_hw) ----
__global__ __launch_bounds__(256) void k_agg(const float* __restrict__ bias,
                                             int n, int relu) {
    int node = blockIdx.x * 4 + (threadIdx.x >> 6);
    int c = threadIdx.x & 63;
    if (node >= n) return;

    int beg = g_rowptr[node];
    int end = g_rowptr[node + 1];
    float d = g_dis[node];
    float acc = g_hw[node * HD + c] * (d * d);   // self-loop term

    int k = beg;
    for (; k + 3 < end; k += 4) {
        int2 e0 = g_edge[k], e1 = g_edge[k + 1], e2 = g_edge[k + 2], e3 = g_edge[k + 3];
        float v0 = __ldg(&g_hw[e0.x * HD + c]);
        float v1 = __ldg(&g_hw[e1.x * HD + c]);
        float v2 = __ldg(&g_hw[e2.x * HD + c]);
        float v3 = __ldg(&g_hw[e3.x * HD + c]);
        acc = fmaf(__int_as_float(e0.y), v0, acc);
        acc = fmaf(__int_as_float(e1.y), v1, acc);
        acc = fmaf(__int_as_float(e2.y), v2, acc);
        acc = fmaf(__int_as_float(e3.y), v3, acc);
    }
    for (; k < end; k++) {
        int2 e0 = g_edge[k];
        acc = fmaf(__int_as_float(e0.y), __ldg(&g_hw[e0.x * HD + c]), acc);
    }

    acc += bias[c];
    if (relu) acc = fmaxf(acc, 0.f);
    g_h[node * HD + c] = acc;
}

// ---- mean pool: batch sorted, accumulate runs in registers, flush on change ----
__global__ void k_pool(const int* __restrict__ batch, int n) {
    int c = threadIdx.x;            // 64 channels
    int n0 = blockIdx.x * 256;
    if (n0 >= n) return;
    int n1 = min(n0 + 256, n);
    int cur = __ldg(&batch[n0]);
    float acc = 0.f, cnt = 0.f;
    for (int nd = n0; nd < n1; nd++) {
        int g = __ldg(&batch[nd]);
        if (g != cur) {
            atomicAdd(&g_pooled[cur * HD + c], acc);
            if (c == 0) atomicAdd(&g_gcnt[cur], cnt);
            acc = 0.f; cnt = 0.f; cur = g;
        }
        acc += g_h[nd * HD + c];
        cnt += 1.f;
    }
    atomicAdd(&g_pooled[cur * HD + c], acc);
    if (c == 0) atomicAdd(&g_gcnt[cur], cnt);
}

// ---- head: out[g][o] = (pooled[g]/cnt[g]) @ Wl + bl ----
__global__ void k_final(const float* __restrict__ Wl, const float* __restrict__ bl,
                        float* __restrict__ out) {
    int g = blockIdx.x;
    int o = threadIdx.x;
    float inv = 1.0f / g_gcnt[g];
    float s = bl[o];
#pragma unroll
    for (int h = 0; h < HD; h++)
        s = fmaf(g_pooled[g * HD + h] * inv, Wl[h * NO + o], s);
    out[g * NO + o] = s;
}

extern "C" void kernel_launch(void* const* d_in, const int* in_sizes, int n_in,
                              void* d_out, int out_size) {
    const float* x  = (const float*)d_in[0];
    const int*   ei = (const int*)  d_in[1];
    const int*   bt = (const int*)  d_in[2];
    const float* W1 = (const float*)d_in[3];
    const float* b1 = (const float*)d_in[4];
    const float* W2 = (const float*)d_in[5];
    const float* b2 = (const float*)d_in[6];
    const float* W3 = (const float*)d_in[7];
    const float* b3 = (const float*)d_in[8];
    const float* Wl = (const float*)d_in[9];
    const float* bl = (const float*)d_in[10];
    float* out = (float*)d_out;

    int n = in_sizes[0] / HD;   // 50000
    int e = in_sizes[1] / 2;    // 800000

    const int tb = 256;
    // CSR build (recomputed every launch; deterministic inputs)
    k_init <<<(n + tb - 1) / tb, tb>>>(n);
    k_count<<<(e + tb - 1) / tb, tb>>>(ei, e);
    k_dis  <<<(n + tb - 1) / tb, tb>>>(n);
    k_scan <<<1, 1024>>>(n);
    k_build<<<(e + tb - 1) / tb, tb>>>(ei, e);

    int gemm_grid = (n + 63) / 64;
    int agg_grid  = (n + 3) / 4;

    // layer 1 (input x)
    k_gemm64<<<gemm_grid, 256>>>(x, W1, n, 1);
    k_agg   <<<agg_grid, 256>>>(b1, n, 1);
    // layer 2 (input g_h)
    k_gemm64<<<gemm_grid, 256>>>(x, W2, n, 0);
    k_agg   <<<agg_grid, 256>>>(b2, n, 1);
    // layer 3 (input g_h, no relu)
    k_gemm64<<<gemm_grid, 256>>>(x, W3, n, 0);
    k_agg   <<<agg_grid, 256>>>(b3, n, 0);

    // pool + head
    k_pool <<<(n + 255) / 256, 64>>>(bt, n);
    k_final<<<NG, NO>>>(Wl, bl, out);
}

// round 16
// speedup vs baseline: 1.0020x; 1.0020x over previous
#include <cuda_runtime.h>

#define MAXN 50000
#define MAXE 800000
#define HD 64
#define NG 64
#define NO 32

// ---- scratch (static device memory; no allocation APIs) ----
__device__ __align__(16) float g_hw[MAXN * HD];   // GEMM output per layer
__device__ __align__(16) float g_h [MAXN * HD];   // aggregated features per layer
__device__ float g_dis[MAXN];                     // rsqrt(deg)
__device__ int   g_deg[MAXN];
__device__ int   g_rowptr[MAXN + 1];
__device__ int   g_cursor[MAXN];
__device__ int2  g_edge[MAXE];                    // (src, bitcast(norm)) bucketed by dst
__device__ float g_pooled[NG * HD];
__device__ float g_gcnt[NG];

// ---- init: zero counters/accumulators ----
__global__ void k_init(int n) {
    int i = blockIdx.x * blockDim.x + threadIdx.x;
    if (i < n)       g_deg[i]    = 0;
    if (i < NG * HD) g_pooled[i] = 0.f;
    if (i < NG)      g_gcnt[i]   = 0.f;
}

// ---- in-degree count (dst row of edge_index) ----
__global__ void k_count(const int* __restrict__ ei, int e) {
    int i = blockIdx.x * blockDim.x + threadIdx.x;
    if (i < e) atomicAdd(&g_deg[ei[e + i]], 1);
}

// ---- dis = rsqrt(deg + 1)  (self-loop) ----
__global__ void k_dis(int n) {
    int i = blockIdx.x * blockDim.x + threadIdx.x;
    if (i < n) g_dis[i] = rsqrtf((float)g_deg[i] + 1.0f);
}

// ---- exclusive scan of degrees -> rowptr, cursor (single block) ----
__global__ __launch_bounds__(1024) void k_scan(int n) {
    __shared__ int part[1024];
    int t = threadIdx.x;
    int ch = (n + 1023) >> 10;
    int base = t * ch;
    int s = 0;
    for (int j = 0; j < ch; j++) {
        int idx = base + j;
        if (idx < n) s += g_deg[idx];
    }
    part[t] = s;
    __syncthreads();
    for (int off = 1; off < 1024; off <<= 1) {
        int v = (t >= off) ? part[t - off] : 0;
        __syncthreads();
        part[t] += v;
        __syncthreads();
    }
    int run = (t == 0) ? 0 : part[t - 1];
    for (int j = 0; j < ch; j++) {
        int idx = base + j;
        if (idx < n) {
            g_rowptr[idx] = run;
            g_cursor[idx] = run;
            run += g_deg[idx];
        }
    }
    if (t == 0) g_rowptr[n] = part[1023];
}

// ---- bucket edges by dst; precompute norm = dis[src]*dis[dst] ----
__global__ void k_build(const int* __restrict__ ei, int e) {
    int i = blockIdx.x * blockDim.x + threadIdx.x;
    if (i >= e) return;
    int s = ei[i];
    int d = ei[e + i];
    int pos = atomicAdd(&g_cursor[d], 1);
    float w = g_dis[s] * g_dis[d];
    g_edge[pos] = make_int2(s, __float_as_int(w));
}

// ---- GEMM: g_hw = in(N,64) @ W(64,64); in = x or g_h ----
__device__ __forceinline__ float4 fma4(float a, float4 w, float4 acc) {
    acc.x = fmaf(a, w.x, acc.x);
    acc.y = fmaf(a, w.y, acc.y);
    acc.z = fmaf(a, w.z, acc.z);
    acc.w = fmaf(a, w.w, acc.w);
    return acc;
}

__global__ __launch_bounds__(256) void k_gemm64(const float* __restrict__ xin,
                                                const float* __restrict__ W,
                                                int n, int use_x) {
    __shared__ float4 Ws[1024];   // W[k][c4] as float4: Ws[k*16 + cg]
    int t = threadIdx.x;
    const float4* W4 = (const float4*)W;
#pragma unroll
    for (int i = 0; i < 4; i++) Ws[t + 256 * i] = W4[t + 256 * i];
    __syncthreads();

    const float4* in4 = (const float4*)(use_x ? xin : (const float*)g_h);
    int cg = t & 15;             // column group: cols 4*cg..4*cg+3
    int rq = t >> 4;             // 0..15
    int r0 = blockIdx.x * 64 + rq;  // rows r0, r0+16, r0+32, r0+48

    float4 z = make_float4(0.f, 0.f, 0.f, 0.f);
    float4 a0 = z, a1 = z, a2 = z, a3 = z;

#pragma unroll 4
    for (int kk = 0; kk < 16; kk++) {
        float4 x0 = (r0      < n) ? __ldg(&in4[(r0     ) * 16 + kk]) : z;
        float4 x1 = (r0 + 16 < n) ? __ldg(&in4[(r0 + 16) * 16 + kk]) : z;
        float4 x2 = (r0 + 32 < n) ? __ldg(&in4[(r0 + 32) * 16 + kk]) : z;
        float4 x3 = (r0 + 48 < n) ? __ldg(&in4[(r0 + 48) * 16 + kk]) : z;
        float4 w0 = Ws[(kk * 4 + 0) * 16 + cg];
        float4 w1 = Ws[(kk * 4 + 1) * 16 + cg];
        float4 w2 = Ws[(kk * 4 + 2) * 16 + cg];
        float4 w3 = Ws[(kk * 4 + 3) * 16 + cg];
        a0 = fma4(x0.x, w0, a0); a0 = fma4(x0.y, w1, a0); a0 = fma4(x0.z, w2, a0); a0 = fma4(x0.w, w3, a0);
        a1 = fma4(x1.x, w0, a1); a1 = fma4(x1.y, w1, a1); a1 = fma4(x1.z, w2, a1); a1 = fma4(x1.w, w3, a1);
        a2 = fma4(x2.x, w0, a2); a2 = fma4(x2.y, w1, a2); a2 = fma4(x2.z, w2, a2); a2 = fma4(x2.w, w3, a2);
        a3 = fma4(x3.x, w0, a3); a3 = fma4(x3.y, w1, a3); a3 = fma4(x3.z, w2, a3); a3 = fma4(x3.w, w3, a3);
    }

    float4* out4 = (float4*)g_hw;
    if (r0      < n) out4[(r0     ) * 16 + cg] = a0;
    if (r0 + 16 < n) out4[(r0 + 16) * 16 + cg] = a1;
    if (r0 + 32 < n) out4[(r0 + 32) * 16 + cg] = a2;
    if (r0 + 48 < n) out4[(r0 + 48) * 16 + cg] = a3;
}

// ---- aggregation (gather over CSR) + bias (+relu): g_h = agg(g_hw) ----
__global__ __launch_bounds__(256) void k_agg(const float* __restrict__ bias,
                                             int n, int relu) {
    int node = blockIdx.x * 4 + (threadIdx.x >> 6);
    int c = threadIdx.x & 63;
    if (node >= n) return;

    int beg = g_rowptr[node];
    int end = g_rowptr[node + 1];
    float d = g_dis[node];
    float acc = g_hw[node * HD + c] * (d * d);   // self-loop term

    int k = beg;
    for (; k + 3 < end; k += 4) {
        int2 e0 = g_edge[k], e1 = g_edge[k + 1], e2 = g_edge[k + 2], e3 = g_edge[k + 3];
        float v0 = __ldg(&g_hw[e0.x * HD + c]);
        float v1 = __ldg(&g_hw[e1.x * HD + c]);
        float v2 = __ldg(&g_hw[e2.x * HD + c]);
        float v3 = __ldg(&g_hw[e3.x * HD + c]);
        acc = fmaf(__int_as_float(e0.y), v0, acc);
        acc = fmaf(__int_as_float(e1.y), v1, acc);
        acc = fmaf(__int_as_float(e2.y), v2, acc);
        acc = fmaf(__int_as_float(e3.y), v3, acc);
    }
    for (; k < end; k++) {
        int2 e0 = g_edge[k];
        acc = fmaf(__int_as_float(e0.y), __ldg(&g_hw[e0.x * HD + c]), acc);
    }

    acc += bias[c];
    if (relu) acc = fmaxf(acc, 0.f);
    g_h[node * HD + c] = acc;
}

// ---- mean pool: batch sorted, accumulate runs in registers, flush on change ----
__global__ void k_pool(const int* __restrict__ batch, int n) {
    int c = threadIdx.x;            // 64 channels
    int n0 = blockIdx.x * 256;
    if (n0 >= n) return;
    int n1 = min(n0 + 256, n);
    int cur = __ldg(&batch[n0]);
    float acc = 0.f, cnt = 0.f;
    for (int nd = n0; nd < n1; nd++) {
        int g = __ldg(&batch[nd]);
        if (g != cur) {
            atomicAdd(&g_pooled[cur * HD + c], acc);
            if (c == 0) atomicAdd(&g_gcnt[cur], cnt);
            acc = 0.f; cnt = 0.f; cur = g;
        }
        acc += g_h[nd * HD + c];
        cnt += 1.f;
    }
    atomicAdd(&g_pooled[cur * HD + c], acc);
    if (c == 0) atomicAdd(&g_gcnt[cur], cnt);
}

// ---- head: out[g][o] = (pooled[g]/cnt[g]) @ Wl + bl ----
__global__ void k_final(const float* __restrict__ Wl, const float* __restrict__ bl,
                        float* __restrict__ out) {
    int g = blockIdx.x;
    int o = threadIdx.x;
    float inv = 1.0f / g_gcnt[g];
    float s = bl[o];
#pragma unroll
    for (int h = 0; h < HD; h++)
        s = fmaf(g_pooled[g * HD + h] * inv, Wl[h * NO + o], s);
    out[g * NO + o] = s;
}

extern "C" void kernel_launch(void* const* d_in, const int* in_sizes, int n_in,
                              void* d_out, int out_size) {
    const float* x  = (const float*)d_in[0];
    const int*   ei = (const int*)  d_in[1];
    const int*   bt = (const int*)  d_in[2];
    const float* W1 = (const float*)d_in[3];
    const float* b1 = (const float*)d_in[4];
    const float* W2 = (const float*)d_in[5];
    const float* b2 = (const float*)d_in[6];
    const float* W3 = (const float*)d_in[7];
    const float* b3 = (const float*)d_in[8];
    const float* Wl = (const float*)d_in[9];
    const float* bl = (const float*)d_in[10];
    float* out = (float*)d_out;

    int n = in_sizes[0] / HD;   // 50000
    int e = in_sizes[1] / 2;    // 800000

    const int tb = 256;
    // CSR build (recomputed every launch; deterministic inputs)
    k_init <<<(n + tb - 1) / tb, tb>>>(n);
    k_count<<<(e + tb - 1) / tb, tb>>>(ei, e);
    k_dis  <<<(n + tb - 1) / tb, tb>>>(n);
    k_scan <<<1, 1024>>>(n);
    k_build<<<(e + tb - 1) / tb, tb>>>(ei, e);

    int gemm_grid = (n + 63) / 64;
    int agg_grid  = (n + 3) / 4;

    // layer 1 (input x)
    k_gemm64<<<gemm_grid, 256>>>(x, W1, n, 1);
    k_agg   <<<agg_grid, 256>>>(b1, n, 1);
    // layer 2 (input g_h)
    k_gemm64<<<gemm_grid, 256>>>(x, W2, n, 0);
    k_agg   <<<agg_grid, 256>>>(b2, n, 1);
    // layer 3 (input g_h, no relu)
    k_gemm64<<<gemm_grid, 256>>>(x, W3, n, 0);
    k_agg   <<<agg_grid, 256>>>(b3, n, 0);

    // pool + head
    k_pool <<<(n + 255) / 256, 64>>>(bt, n);
    k_final<<<NG, NO>>>(Wl, bl, out);
}

// round 17
// speedup vs baseline: 1.0086x; 1.0066x over previous
#include <cuda_runtime.h>

#define MAXN 50000
#define MAXE 800000
#define HD 64
#define NG 64
#define NO 32

// ---- scratch (static device memory; no allocation APIs) ----
__device__ __align__(16) float g_hw[MAXN * HD];   // GEMM output per layer
__device__ __align__(16) float g_h [MAXN * HD];   // aggregated features per layer
__device__ float g_dis[MAXN];                     // rsqrt(deg)
__device__ int   g_deg[MAXN];
__device__ int   g_rowptr[MAXN + 1];
__device__ int   g_cursor[MAXN];
__device__ int2  g_edge[MAXE];                    // (src, bitcast(norm)) bucketed by dst
__device__ float g_pooled[NG * HD];
__device__ float g_gcnt[NG];

// ---- init: zero counters/accumulators ----
__global__ void k_init(int n) {
    int i = blockIdx.x * blockDim.x + threadIdx.x;
    if (i < n)       g_deg[i]    = 0;
    if (i < NG * HD) g_pooled[i] = 0.f;
    if (i < NG)      g_gcnt[i]   = 0.f;
}

// ---- in-degree count (dst row of edge_index) ----
__global__ void k_count(const int* __restrict__ ei, int e) {
    int i = blockIdx.x * blockDim.x + threadIdx.x;
    if (i < e) atomicAdd(&g_deg[ei[e + i]], 1);
}

// ---- dis = rsqrt(deg + 1)  (self-loop) ----
__global__ void k_dis(int n) {
    int i = blockIdx.x * blockDim.x + threadIdx.x;
    if (i < n) g_dis[i] = rsqrtf((float)g_deg[i] + 1.0f);
}

// ---- exclusive scan of degrees -> rowptr, cursor (single block) ----
__global__ __launch_bounds__(1024) void k_scan(int n) {
    __shared__ int part[1024];
    int t = threadIdx.x;
    int ch = (n + 1023) >> 10;
    int base = t * ch;
    int s = 0;
    for (int j = 0; j < ch; j++) {
        int idx = base + j;
        if (idx < n) s += g_deg[idx];
    }
    part[t] = s;
    __syncthreads();
    for (int off = 1; off < 1024; off <<= 1) {
        int v = (t >= off) ? part[t - off] : 0;
        __syncthreads();
        part[t] += v;
        __syncthreads();
    }
    int run = (t == 0) ? 0 : part[t - 1];
    for (int j = 0; j < ch; j++) {
        int idx = base + j;
        if (idx < n) {
            g_rowptr[idx] = run;
            g_cursor[idx] = run;
            run += g_deg[idx];
        }
    }
    if (t == 0) g_rowptr[n] = part[1023];
}

// ---- bucket edges by dst; precompute norm = dis[src]*dis[dst] ----
__global__ void k_build(const int* __restrict__ ei, int e) {
    int i = blockIdx.x * blockDim.x + threadIdx.x;
    if (i >= e) return;
    int s = ei[i];
    int d = ei[e + i];
    int pos = atomicAdd(&g_cursor[d], 1);
    float w = g_dis[s] * g_dis[d];
    g_edge[pos] = make_int2(s, __float_as_int(w));
}

// ---- GEMM: g_hw = in(N,64) @ W(64,64); in = x or g_h ----
__device__ __forceinline__ float4 fma4(float a, float4 w, float4 acc) {
    acc.x = fmaf(a, w.x, acc.x);
    acc.y = fmaf(a, w.y, acc.y);
    acc.z = fmaf(a, w.z, acc.z);
    acc.w = fmaf(a, w.w, acc.w);
    return acc;
}

__global__ __launch_bounds__(256) void k_gemm64(const float* __restrict__ xin,
                                                const float* __restrict__ W,
                                                int n, int use_x) {
    __shared__ float4 Ws[1024];   // W[k][c4] as float4: Ws[k*16 + cg]
    int t = threadIdx.x;
    const float4* W4 = (const float4*)W;
#pragma unroll
    for (int i = 0; i < 4; i++) Ws[t + 256 * i] = W4[t + 256 * i];
    __syncthreads();

    const float4* in4 = (const float4*)(use_x ? xin : (const float*)g_h);
    int cg = t & 15;             // column group: cols 4*cg..4*cg+3
    int rq = t >> 4;             // 0..15
    int r0 = blockIdx.x * 64 + rq;  // rows r0, r0+16, r0+32, r0+48

    float4 z = make_float4(0.f, 0.f, 0.f, 0.f);
    float4 a0 = z, a1 = z, a2 = z, a3 = z;

#pragma unroll 4
    for (int kk = 0; kk < 16; kk++) {
        float4 x0 = (r0      < n) ? __ldg(&in4[(r0     ) * 16 + kk]) : z;
        float4 x1 = (r0 + 16 < n) ? __ldg(&in4[(r0 + 16) * 16 + kk]) : z;
        float4 x2 = (r0 + 32 < n) ? __ldg(&in4[(r0 + 32) * 16 + kk]) : z;
        float4 x3 = (r0 + 48 < n) ? __ldg(&in4[(r0 + 48) * 16 + kk]) : z;
        float4 w0 = Ws[(kk * 4 + 0) * 16 + cg];
        float4 w1 = Ws[(kk * 4 + 1) * 16 + cg];
        float4 w2 = Ws[(kk * 4 + 2) * 16 + cg];
        float4 w3 = Ws[(kk * 4 + 3) * 16 + cg];
        a0 = fma4(x0.x, w0, a0); a0 = fma4(x0.y, w1, a0); a0 = fma4(x0.z, w2, a0); a0 = fma4(x0.w, w3, a0);
        a1 = fma4(x1.x, w0, a1); a1 = fma4(x1.y, w1, a1); a1 = fma4(x1.z, w2, a1); a1 = fma4(x1.w, w3, a1);
        a2 = fma4(x2.x, w0, a2); a2 = fma4(x2.y, w1, a2); a2 = fma4(x2.z, w2, a2); a2 = fma4(x2.w, w3, a2);
        a3 = fma4(x3.x, w0, a3); a3 = fma4(x3.y, w1, a3); a3 = fma4(x3.z, w2, a3); a3 = fma4(x3.w, w3, a3);
    }

    float4* out4 = (float4*)g_hw;
    if (r0      < n) out4[(r0     ) * 16 + cg] = a0;
    if (r0 + 16 < n) out4[(r0 + 16) * 16 + cg] = a1;
    if (r0 + 32 < n) out4[(r0 + 32) * 16 + cg] = a2;
    if (r0 + 48 < n) out4[(r0 + 48) * 16 + cg] = a3;
}

// ---- aggregation (gather over CSR) + bias (+relu): g_h = agg(g_hw) ----
__global__ __launch_bounds__(256) void k_agg(const float* __restrict__ bias,
                                             int n, int relu) {
    int node = blockIdx.x * 4 + (threadIdx.x >> 6);
    int c = threadIdx.x & 63;
    if (node >= n) return;

    int beg = g_rowptr[node];
    int end = g_rowptr[node + 1];
    float d = g_dis[node];
    float acc = g_hw[node * HD + c] * (d * d);   // self-loop term

    int k = beg;
    for (; k + 3 < end; k += 4) {
        int2 e0 = g_edge[k], e1 = g_edge[k + 1], e2 = g_edge[k + 2], e3 = g_edge[k + 3];
        float v0 = __ldg(&g_hw[e0.x * HD + c]);
        float v1 = __ldg(&g_hw[e1.x * HD + c]);
        float v2 = __ldg(&g_hw[e2.x * HD + c]);
        float v3 = __ldg(&g_hw[e3.x * HD + c]);
        acc = fmaf(__int_as_float(e0.y), v0, acc);
        acc = fmaf(__int_as_float(e1.y), v1, acc);
        acc = fmaf(__int_as_float(e2.y), v2, acc);
        acc = fmaf(__int_as_float(e3.y), v3, acc);
    }
    for (; k < end; k++) {
        int2 e0 = g_edge[k];
        acc = fmaf(__int_as_float(e0.y), __ldg(&g_hw[e0.x * HD + c]), acc);
    }

    acc += bias[c];
    if (relu) acc = fmaxf(acc, 0.f);
    g_h[node * HD + c] = acc;
}

// ---- mean pool: batch sorted, accumulate runs in registers, flush on change ----
__global__ void k_pool(const int* __restrict__ batch, int n) {
    int c = threadIdx.x;            // 64 channels
    int n0 = blockIdx.x * 256;
    if (n0 >= n) return;
    int n1 = min(n0 + 256, n);
    int cur = __ldg(&batch[n0]);
    float acc = 0.f, cnt = 0.f;
    for (int nd = n0; nd < n1; nd++) {
        int g = __ldg(&batch[nd]);
        if (g != cur) {
            atomicAdd(&g_pooled[cur * HD + c], acc);
            if (c == 0) atomicAdd(&g_gcnt[cur], cnt);
            acc = 0.f; cnt = 0.f; cur = g;
        }
        acc += g_h[nd * HD + c];
        cnt += 1.f;
    }
    atomicAdd(&g_pooled[cur * HD + c], acc);
    if (c == 0) atomicAdd(&g_gcnt[cur], cnt);
}

// ---- head: out[g][o] = (pooled[g]/cnt[g]) @ Wl + bl ----
__global__ void k_final(const float* __restrict__ Wl, const float* __restrict__ bl,
                        float* __restrict__ out) {
    int g = blockIdx.x;
    int o = threadIdx.x;
    float inv = 1.0f / g_gcnt[g];
    float s = bl[o];
#pragma unroll
    for (int h = 0; h < HD; h++)
        s = fmaf(g_pooled[g * HD + h] * inv, Wl[h * NO + o], s);
    out[g * NO + o] = s;
}

extern "C" void kernel_launch(void* const* d_in, const int* in_sizes, int n_in,
                              void* d_out, int out_size) {
    const float* x  = (const float*)d_in[0];
    const int*   ei = (const int*)  d_in[1];
    const int*   bt = (const int*)  d_in[2];
    const float* W1 = (const float*)d_in[3];
    const float* b1 = (const float*)d_in[4];
    const float* W2 = (const float*)d_in[5];
    const float* b2 = (const float*)d_in[6];
    const float* W3 = (const float*)d_in[7];
    const float* b3 = (const float*)d_in[8];
    const float* Wl = (const float*)d_in[9];
    const float* bl = (const float*)d_in[10];
    float* out = (float*)d_out;

    int n = in_sizes[0] / HD;   // 50000
    int e = in_sizes[1] / 2;    // 800000

    const int tb = 256;
    // CSR build (recomputed every launch; deterministic inputs)
    k_init <<<(n + tb - 1) / tb, tb>>>(n);
    k_count<<<(e + tb - 1) / tb, tb>>>(ei, e);
    k_dis  <<<(n + tb - 1) / tb, tb>>>(n);
    k_scan <<<1, 1024>>>(n);
    k_build<<<(e + tb - 1) / tb, tb>>>(ei, e);

    int gemm_grid = (n + 63) / 64;
    int agg_grid  = (n + 3) / 4;

    // layer 1 (input x)
    k_gemm64<<<gemm_grid, 256>>>(x, W1, n, 1);
    k_agg   <<<agg_grid, 256>>>(b1, n, 1);
    // layer 2 (input g_h)
    k_gemm64<<<gemm_grid, 256>>>(x, W2, n, 0);
    k_agg   <<<agg_grid, 256>>>(b2, n, 1);
    // layer 3 (input g_h, no relu)
    k_gemm64<<<gemm_grid, 256>>>(x, W3, n, 0);
    k_agg   <<<agg_grid, 256>>>(b3, n, 0);

    // pool + head
    k_pool <<<(n + 255) / 256, 64>>>(bt, n);
    k_final<<<NG, NO>>>(Wl, bl, out);
}